// round 7
// baseline (speedup 1.0000x reference)
#include <cuda_runtime.h>

#define N_NODES 2048
#define F_IN    64
#define H_DIM   16
#define O_DIM   8

#define R_BLK   4                       // rows per k_main block
#define TILE_J  512                     // j-tile
#define N_TILES (N_NODES / TILE_J)      // 4
#define TPAD    (TILE_J + 8)            // +8 floats: conflict-free smem rows

// -------- scratch (no allocations allowed) --------
__device__ float g_fsums[N_NODES * O_DIM];

// ============================================================================
// cp.async helpers (LDGSTS .cg 16B — streaming, bypasses L1)
// ============================================================================
__device__ __forceinline__ void cp16(void* smem_dst, const void* gmem_src) {
    unsigned s = (unsigned)__cvta_generic_to_shared(smem_dst);
    asm volatile("cp.async.cg.shared.global [%0], [%1], 16;\n" :: "r"(s), "l"(gmem_src));
}
__device__ __forceinline__ void cp_commit() { asm volatile("cp.async.commit_group;\n"); }
__device__ __forceinline__ void cp_wait1()  { asm volatile("cp.async.wait_group 1;\n"); }
__device__ __forceinline__ void cp_wait0()  { asm volatile("cp.async.wait_group 0;\n"); }

// ============================================================================
// Kernel 1: k_fsum — f branch. grid=32, block=256, 64 nodes/block.
// Each block inlines the f-fold (coalesced flat-float4 weight reads + shuffle
// reduce; weights L2-hot after the first wave), then does the relu-split GEMV:
//   fx[o] = max(x,0)*A+[f,o] + min(x,0)*A-[f,o]   (exact for zero biases)
// Thread layout: node = blk*64 + tid>>2, feature quarter = (tid&3)*16.
// Slow path: honest full per-feature MLP chain (gated on biases != 0).
// ============================================================================
__global__ void __launch_bounds__(256)
k_fsum(const float* __restrict__ x,
       const float* __restrict__ fW1, const float* __restrict__ fb1,
       const float* __restrict__ fW2, const float* __restrict__ fb2,
       const float* __restrict__ fW3, const float* __restrict__ fb3)
{
    __shared__ float s_w1p[F_IN * H_DIM], s_w1n[F_IN * H_DIM];
    __shared__ float s_cp[F_IN * H_DIM],  s_cn[F_IN * H_DIM];
    __shared__ float s_A[F_IN * 16];     // [f*16+o]=A+, [f*16+8+o]=A-

    const int tid = threadIdx.x;

    // ---- runtime guard: all f-biases zero? (coalesced strided) ----
    int nz = 0;
    for (int i = tid; i < F_IN * H_DIM; i += 256)
        nz |= (fb1[i] != 0.0f) | (fb2[i] != 0.0f);
    for (int i = tid; i < F_IN * O_DIM; i += 256)
        nz |= (fb3[i] != 0.0f);
    const int any_nz = __syncthreads_or(nz);

    const int node  = blockIdx.x * 64 + (tid >> 2);
    const int fbase = (tid & 3) * 16;

    float acc[O_DIM];
    #pragma unroll
    for (int o = 0; o < O_DIM; o++) acc[o] = 0.0f;

    if (!any_nz) {
        // ---- stage relu'd W1 (coalesced) ----
        for (int i = tid; i < F_IN * H_DIM; i += 256) {
            const float w = fW1[i];
            s_w1p[i] = fmaxf(w, 0.0f);
            s_w1n[i] = fminf(w, 0.0f);
        }
        __syncthreads();

        // ---- c pass: c±[f,g] = sum_h fW2[f,g,h]*w1±[f,h] (flat float4) ----
        {
            const float4* W2 = (const float4*)fW2;   // 4096 float4
            #pragma unroll 4
            for (int k = 0; k < 16; k++) {
                const int idx = k * 256 + tid;
                const float4 v = __ldg(W2 + idx);
                const int f  = idx >> 6;             // 64 float4 per f
                const int hb = (idx & 3) * 4;
                const float* wp = s_w1p + f * H_DIM + hb;
                const float* wn = s_w1n + f * H_DIM + hb;
                float cp = v.x*wp[0] + v.y*wp[1] + v.z*wp[2] + v.w*wp[3];
                float cn = v.x*wn[0] + v.y*wn[1] + v.z*wn[2] + v.w*wn[3];
                cp += __shfl_xor_sync(0xFFFFFFFFu, cp, 1);
                cp += __shfl_xor_sync(0xFFFFFFFFu, cp, 2);
                cn += __shfl_xor_sync(0xFFFFFFFFu, cn, 1);
                cn += __shfl_xor_sync(0xFFFFFFFFu, cn, 2);
                if ((tid & 3) == 0) { s_cp[idx >> 2] = cp; s_cn[idx >> 2] = cn; }
            }
        }
        __syncthreads();

        // ---- A pass: A±[f,o] = sum_g fW3[f,o,g]*relu±(c±[f,g]) ----
        {
            const float4* W3 = (const float4*)fW3;   // 2048 float4
            #pragma unroll 4
            for (int k = 0; k < 8; k++) {
                const int j = k * 256 + tid;
                const float4 v = __ldg(W3 + j);
                const int f  = j >> 5;               // 32 float4 per f
                const int o  = (j >> 2) & 7;
                const int gb = (j & 3) * 4;
                const float* cpp = s_cp + f * H_DIM + gb;
                const float* cnn = s_cn + f * H_DIM + gb;
                float ap = v.x*fmaxf(cpp[0],0.f) + v.y*fmaxf(cpp[1],0.f)
                         + v.z*fmaxf(cpp[2],0.f) + v.w*fmaxf(cpp[3],0.f);
                float an = v.x*fminf(cnn[0],0.f) + v.y*fminf(cnn[1],0.f)
                         + v.z*fminf(cnn[2],0.f) + v.w*fminf(cnn[3],0.f);
                ap += __shfl_xor_sync(0xFFFFFFFFu, ap, 1);
                ap += __shfl_xor_sync(0xFFFFFFFFu, ap, 2);
                an += __shfl_xor_sync(0xFFFFFFFFu, an, 1);
                an += __shfl_xor_sync(0xFFFFFFFFu, an, 2);
                if ((tid & 3) == 0) {
                    s_A[f * 16 + o]     = ap;
                    s_A[f * 16 + 8 + o] = an;
                }
            }
        }
        __syncthreads();

        // ---- relu-split GEMV: this thread's 16 features of its node ----
        const float4* xr = (const float4*)(x + (size_t)node * F_IN + fbase);
        #pragma unroll
        for (int q = 0; q < 4; q++) {
            const float4 v = __ldg(xr + q);
            const float xv[4] = { v.x, v.y, v.z, v.w };
            #pragma unroll
            for (int u = 0; u < 4; u++) {
                const int   f  = fbase + q * 4 + u;
                const float xp = fmaxf(xv[u], 0.0f);
                const float xn = fminf(xv[u], 0.0f);
                #pragma unroll
                for (int o = 0; o < O_DIM; o++)
                    acc[o] = fmaf(xp, s_A[f * 16 + o], fmaf(xn, s_A[f * 16 + 8 + o], acc[o]));
            }
        }
    } else {
        // ---- honest fallback: full per-feature MLP chain ----
        for (int ff = 0; ff < 16; ff++) {
            const int   f  = fbase + ff;
            const float xv = x[(size_t)node * F_IN + f];
            float h1[H_DIM];
            #pragma unroll
            for (int k = 0; k < H_DIM; k++)
                h1[k] = fmaxf(fmaf(xv, __ldg(fW1 + f*H_DIM + k), __ldg(fb1 + f*H_DIM + k)), 0.0f);
            float h2[H_DIM];
            #pragma unroll
            for (int g = 0; g < H_DIM; g++) {
                float s = __ldg(fb2 + f*H_DIM + g);
                #pragma unroll
                for (int k = 0; k < H_DIM; k++)
                    s = fmaf(__ldg(fW2 + (f*H_DIM + g)*H_DIM + k), h1[k], s);
                h2[g] = fmaxf(s, 0.0f);
            }
            #pragma unroll
            for (int o = 0; o < O_DIM; o++) {
                float s = __ldg(fb3 + f*O_DIM + o);
                #pragma unroll
                for (int k = 0; k < H_DIM; k++)
                    s = fmaf(__ldg(fW3 + (f*O_DIM + o)*H_DIM + k), h2[k], s);
                acc[o] += s;
            }
        }
    }

    // ---- reduce 4 feature-quarter threads per node ----
    #pragma unroll
    for (int o = 0; o < O_DIM; o++) {
        acc[o] += __shfl_xor_sync(0xFFFFFFFFu, acc[o], 1);
        acc[o] += __shfl_xor_sync(0xFFFFFFFFu, acc[o], 2);
    }
    if ((tid & 3) == 0) {
        #pragma unroll
        for (int o = 0; o < O_DIM; o++)
            g_fsums[node * O_DIM + o] = acc[o];
    }
}

// ============================================================================
// Helper: full scalar m-MLP (fallback only)
// ============================================================================
__device__ __forceinline__ float m_eval_full(float d,
    const float* sw1, const float* sb1, const float* sw2,
    const float* sb2, const float* sw3, float b3)
{
    float h1[H_DIM];
    #pragma unroll
    for (int k = 0; k < H_DIM; k++)
        h1[k] = fmaxf(fmaf(d, sw1[k], sb1[k]), 0.0f);
    float m = b3;
    #pragma unroll
    for (int g = 0; g < H_DIM; g++) {
        float s = sb2[g];
        #pragma unroll
        for (int k = 0; k < H_DIM; k++)
            s = fmaf(sw2[g * H_DIM + k], h1[k], s);
        m = fmaf(sw3[g], fmaxf(s, 0.0f), m);
    }
    return m;
}

// ============================================================================
// Kernel 2: k_main — pred[i,:] = sum_j (m(d)/norm) * f_sums[j,:]
// grid=512, block=256, R=4 rows. m-fold inlined in warp 0 (weights L2-hot).
// Transposed lane layout:
//   w-role:   lane -> (row = lane>>3, jj = lane&7)
//   acc-role: lane -> (jq  = lane>>3, o  = lane&7), acc[4] scalars/thread
// d/norm stream via cp.async double-buffered smem tiles; f_sums read as
// consecutive-128B warp LDGs (L1-resident); w broadcast via shuffles.
// ============================================================================
__global__ void __launch_bounds__(256)
k_main(const float* __restrict__ dmat, const float* __restrict__ nmat,
       const float* __restrict__ mW1, const float* __restrict__ mb1,
       const float* __restrict__ mW2, const float* __restrict__ mb2,
       const float* __restrict__ mW3, const float* __restrict__ mb3,
       float* __restrict__ out)
{
    __shared__ float s_d[2][R_BLK * TPAD];
    __shared__ float s_n[2][R_BLK * TPAD];
    __shared__ float s_part[8][32];
    __shared__ float s_ap, s_an, s_beta;
    __shared__ int   s_fast;
    __shared__ float sw1[H_DIM], sb1v[H_DIM], sw2[H_DIM * H_DIM], sb2v[H_DIM], sw3[H_DIM];

    const int tid  = threadIdx.x;
    const int warp = tid >> 5;
    const int lane = tid & 31;
    const int i0   = blockIdx.x * R_BLK;

    // ---- stage tile 0 FIRST (overlap DRAM fetch with the m-fold) ----
    {
        #pragma unroll
        for (int k = 0; k < 2; k++) {
            const int idx = k * 256 + tid;          // 512 float4 per matrix
            const int r   = idx >> 7;
            const int c4  = (idx & 127) * 4;
            cp16(&s_d[0][r * TPAD + c4], dmat + (size_t)(i0 + r) * N_NODES + c4);
            cp16(&s_n[0][r * TPAD + c4], nmat + (size_t)(i0 + r) * N_NODES + c4);
        }
        cp_commit();
    }

    // ---- warp 0: inline m-fold + zero-bias check ----
    if (tid < 32) {
        const int g = lane & 15;
        float cp = 0.0f, cn = 0.0f;
        #pragma unroll
        for (int h = 0; h < H_DIM; h++) {
            const float w2 = __ldg(mW2 + g * H_DIM + h);
            const float w1 = __ldg(mW1 + h);
            cp = fmaf(w2, fmaxf(w1, 0.0f), cp);
            cn = fmaf(w2, fminf(w1, 0.0f), cn);
        }
        const float w3 = __ldg(mW3 + g);
        float ap = (lane < 16) ? w3 * fmaxf(cp, 0.0f) : 0.0f;
        float an = (lane < 16) ? w3 * fminf(cn, 0.0f) : 0.0f;
        #pragma unroll
        for (int off = 8; off > 0; off >>= 1) {
            ap += __shfl_xor_sync(0x0000FFFFu, ap, off);
            an += __shfl_xor_sync(0x0000FFFFu, an, off);
        }
        int z = (__ldg(mb1 + g) == 0.0f) & (__ldg(mb2 + g) == 0.0f);
        z = __all_sync(0xFFFFFFFFu, z);
        if (lane == 0) { s_ap = ap; s_an = an; s_beta = __ldg(mb3); s_fast = z; }
    }
    __syncthreads();

    const int   mfast = s_fast;
    const float f_ap = s_ap, f_an = s_an, f_be = s_beta;

    if (!mfast) {                        // uniform branch: barrier safe
        if (tid < H_DIM) {
            sw1[tid]  = mW1[tid]; sb1v[tid] = mb1[tid];
            sb2v[tid] = mb2[tid]; sw3[tid]  = mW3[tid];
        }
        sw2[tid] = mW2[tid];
        __syncthreads();
    }
    const float b3v = mfast ? 0.0f : mb3[0];

    float acc[R_BLK] = {0.0f, 0.0f, 0.0f, 0.0f};
    const int lhi = lane >> 3;           // row (w-role) == jq (acc-role)
    const int llo = lane & 7;            // jj (w-role) == o  (acc-role)

    for (int t = 0; t < N_TILES; t++) {
        const int cbuf = t & 1;
        if (t + 1 < N_TILES) {
            const int nbuf = (t + 1) & 1;
            const int jb   = (t + 1) * TILE_J;
            #pragma unroll
            for (int k = 0; k < 2; k++) {
                const int idx = k * 256 + tid;
                const int r   = idx >> 7;
                const int c4  = (idx & 127) * 4;
                cp16(&s_d[nbuf][r * TPAD + c4], dmat + (size_t)(i0 + r) * N_NODES + jb + c4);
                cp16(&s_n[nbuf][r * TPAD + c4], nmat + (size_t)(i0 + r) * N_NODES + jb + c4);
            }
            cp_commit();
            cp_wait1();
        } else {
            cp_wait0();
        }
        __syncthreads();

        const float* __restrict__ sd = s_d[cbuf];
        const float* __restrict__ sn = s_n[cbuf];
        const int colbase = warp * (TILE_J / 8);

        #pragma unroll
        for (int g = 0; g < 8; g++) {
            const int col = colbase + g * 8;
            const float dv = sd[lhi * TPAD + col + llo];
            const float nv = sn[lhi * TPAD + col + llo];
            float wv;
            if (mfast) {
                const float m = fmaf(f_ap, fmaxf(dv, 0.0f),
                                fmaf(f_an, fminf(dv, 0.0f), f_be));
                wv = __fdividef(m, nv);
            } else {
                wv = __fdividef(m_eval_full(dv, sw1, sb1v, sw2, sb2v, sw3, b3v), nv);
            }
            const int base8 = (t * TILE_J + col) * O_DIM;
            #pragma unroll
            for (int u = 0; u < 2; u++) {
                const float fsv = __ldg(g_fsums + base8 + u * 32 + lane);
                #pragma unroll
                for (int r2 = 0; r2 < R_BLK; r2++) {
                    const float wr = __shfl_sync(0xFFFFFFFFu, wv, r2 * 8 + u * 4 + lhi);
                    acc[r2] = fmaf(wr, fsv, acc[r2]);
                }
            }
        }
        __syncthreads();                 // compute done before buffer reuse
    }

    // ---- reduce over jq (lanes sharing o), then across warps ----
    #pragma unroll
    for (int r = 0; r < R_BLK; r++) {
        acc[r] += __shfl_xor_sync(0xFFFFFFFFu, acc[r], 8);
        acc[r] += __shfl_xor_sync(0xFFFFFFFFu, acc[r], 16);
    }
    if (lane < 8) {
        #pragma unroll
        for (int r = 0; r < R_BLK; r++)
            s_part[warp][r * 8 + lane] = acc[r];
    }
    __syncthreads();
    if (tid < 32) {
        float s = 0.0f;
        #pragma unroll
        for (int w = 0; w < 8; w++) s += s_part[w][tid];
        out[i0 * O_DIM + tid] = s;       // tid = r*8+o
    }
}

// ============================================================================
// launch — 2 kernels only
// ============================================================================
extern "C" void kernel_launch(void* const* d_in, const int* in_sizes, int n_in,
                              void* d_out, int out_size)
{
    const float* x   = (const float*)d_in[0];
    const float* dm  = (const float*)d_in[1];
    const float* nm  = (const float*)d_in[2];
    const float* fW1 = (const float*)d_in[3];
    const float* fb1 = (const float*)d_in[4];
    const float* fW2 = (const float*)d_in[5];
    const float* fb2 = (const float*)d_in[6];
    const float* fW3 = (const float*)d_in[7];
    const float* fb3 = (const float*)d_in[8];
    const float* mW1 = (const float*)d_in[9];
    const float* mb1 = (const float*)d_in[10];
    const float* mW2 = (const float*)d_in[11];
    const float* mb2 = (const float*)d_in[12];
    const float* mW3 = (const float*)d_in[13];
    const float* mb3 = (const float*)d_in[14];
    float* out = (float*)d_out;

    k_fsum<<<32, 256>>>(x, fW1, fb1, fW2, fb2, fW3, fb3);
    k_main<<<512, 256>>>(dm, nm, mW1, mb1, mW2, mb2, mW3, mb3, out);
}

// round 9
// speedup vs baseline: 1.4993x; 1.4993x over previous
#include <cuda_runtime.h>

#define N_NODES 2048
#define F_IN    64
#define H_DIM   16
#define O_DIM   8
#define R_BLK   4

typedef unsigned long long ull;

// -------- scratch (no allocations allowed) --------
__device__ float g_fsums[N_NODES * O_DIM];

// ============================================================================
// f32x2 packed helpers (PTX ISA 8.6, sm_100+). Register-only asm is safe;
// memory accesses go through typed C++ loads so the compiler sees the
// dependence on the smem staging stores / barriers (R8 bug: raw ld.shared
// asm without "memory" clobber was reordered across __syncthreads()).
// ============================================================================
__device__ __forceinline__ ull fma2(ull a, ull b, ull c) {
    ull d;
    asm("fma.rn.f32x2 %0, %1, %2, %3;" : "=l"(d) : "l"(a), "l"(b), "l"(c));
    return d;
}
__device__ __forceinline__ ull pack2(float v) {
    ull d;
    asm("mov.b64 %0, {%1, %1};" : "=l"(d) : "f"(v));
    return d;
}
__device__ __forceinline__ void unpack2(ull p, float& lo, float& hi) {
    asm("mov.b64 {%0, %1}, %2;" : "=f"(lo), "=f"(hi) : "l"(p));
}

// ============================================================================
// Kernel 1: k_fsum — grid=128, block=256, 16 nodes/block.
// Per-block inline f-fold (coalesced flat-float4 + shuffle reduce; weights
// L2-hot), then relu-split GEMV:
//   fx[o] = max(x,0)*A+[f,o] + min(x,0)*A-[f,o]   (exact for zero biases)
// Slow path: honest full per-feature MLP chain.
// ============================================================================
__global__ void __launch_bounds__(256)
k_fsum(const float* __restrict__ x,
       const float* __restrict__ fW1, const float* __restrict__ fb1,
       const float* __restrict__ fW2, const float* __restrict__ fb2,
       const float* __restrict__ fW3, const float* __restrict__ fb3)
{
    __shared__ float s_w1p[F_IN * H_DIM], s_w1n[F_IN * H_DIM];
    __shared__ float s_cp[F_IN * H_DIM],  s_cn[F_IN * H_DIM];
    __shared__ float s_A[F_IN * 16];     // [f*16+o]=A+, [f*16+8+o]=A-

    const int tid = threadIdx.x;

    int nz = 0;
    for (int i = tid; i < F_IN * H_DIM; i += 256)
        nz |= (fb1[i] != 0.0f) | (fb2[i] != 0.0f);
    for (int i = tid; i < F_IN * O_DIM; i += 256)
        nz |= (fb3[i] != 0.0f);
    const int any_nz = __syncthreads_or(nz);

    const int node  = blockIdx.x * 16 + (tid >> 4);
    const int fbase = (tid & 15) * 4;

    float acc[O_DIM];
    #pragma unroll
    for (int o = 0; o < O_DIM; o++) acc[o] = 0.0f;

    if (!any_nz) {
        for (int i = tid; i < F_IN * H_DIM; i += 256) {
            const float w = fW1[i];
            s_w1p[i] = fmaxf(w, 0.0f);
            s_w1n[i] = fminf(w, 0.0f);
        }
        __syncthreads();

        {   // c pass: c±[f,g] = sum_h fW2[f,g,h]*w1±[f,h]
            const float4* W2 = (const float4*)fW2;   // 4096 float4
            #pragma unroll 4
            for (int k = 0; k < 16; k++) {
                const int idx = k * 256 + tid;
                const float4 v = __ldg(W2 + idx);
                const int f  = idx >> 6;
                const int hb = (idx & 3) * 4;
                const float* wp = s_w1p + f * H_DIM + hb;
                const float* wn = s_w1n + f * H_DIM + hb;
                float cp = v.x*wp[0] + v.y*wp[1] + v.z*wp[2] + v.w*wp[3];
                float cn = v.x*wn[0] + v.y*wn[1] + v.z*wn[2] + v.w*wn[3];
                cp += __shfl_xor_sync(0xFFFFFFFFu, cp, 1);
                cp += __shfl_xor_sync(0xFFFFFFFFu, cp, 2);
                cn += __shfl_xor_sync(0xFFFFFFFFu, cn, 1);
                cn += __shfl_xor_sync(0xFFFFFFFFu, cn, 2);
                if ((tid & 3) == 0) { s_cp[idx >> 2] = cp; s_cn[idx >> 2] = cn; }
            }
        }
        __syncthreads();

        {   // A pass: A±[f,o] = sum_g fW3[f,o,g]*relu±(c±[f,g])
            const float4* W3 = (const float4*)fW3;   // 2048 float4
            #pragma unroll 4
            for (int k = 0; k < 8; k++) {
                const int j = k * 256 + tid;
                const float4 v = __ldg(W3 + j);
                const int f  = j >> 5;
                const int o  = (j >> 2) & 7;
                const int gb = (j & 3) * 4;
                const float* cpp = s_cp + f * H_DIM + gb;
                const float* cnn = s_cn + f * H_DIM + gb;
                float ap = v.x*fmaxf(cpp[0],0.f) + v.y*fmaxf(cpp[1],0.f)
                         + v.z*fmaxf(cpp[2],0.f) + v.w*fmaxf(cpp[3],0.f);
                float an = v.x*fminf(cnn[0],0.f) + v.y*fminf(cnn[1],0.f)
                         + v.z*fminf(cnn[2],0.f) + v.w*fminf(cnn[3],0.f);
                ap += __shfl_xor_sync(0xFFFFFFFFu, ap, 1);
                ap += __shfl_xor_sync(0xFFFFFFFFu, ap, 2);
                an += __shfl_xor_sync(0xFFFFFFFFu, an, 1);
                an += __shfl_xor_sync(0xFFFFFFFFu, an, 2);
                if ((tid & 3) == 0) {
                    s_A[f * 16 + o]     = ap;
                    s_A[f * 16 + 8 + o] = an;
                }
            }
        }
        __syncthreads();

        const float4 xv4 = __ldg((const float4*)(x + (size_t)node * F_IN + fbase));
        const float xv[4] = { xv4.x, xv4.y, xv4.z, xv4.w };
        #pragma unroll
        for (int ff = 0; ff < 4; ff++) {
            const int   f  = fbase + ff;
            const float xp = fmaxf(xv[ff], 0.0f);
            const float xn = fminf(xv[ff], 0.0f);
            #pragma unroll
            for (int o = 0; o < O_DIM; o++)
                acc[o] = fmaf(xp, s_A[f * 16 + o], fmaf(xn, s_A[f * 16 + 8 + o], acc[o]));
        }
    } else {
        // honest fallback: full per-feature MLP chain
        for (int ff = 0; ff < 4; ff++) {
            const int   f  = fbase + ff;
            const float xv = x[(size_t)node * F_IN + f];
            float h1[H_DIM];
            #pragma unroll
            for (int k = 0; k < H_DIM; k++)
                h1[k] = fmaxf(fmaf(xv, __ldg(fW1 + f*H_DIM + k), __ldg(fb1 + f*H_DIM + k)), 0.0f);
            float h2[H_DIM];
            #pragma unroll
            for (int g = 0; g < H_DIM; g++) {
                float s = __ldg(fb2 + f*H_DIM + g);
                #pragma unroll
                for (int k = 0; k < H_DIM; k++)
                    s = fmaf(__ldg(fW2 + (f*H_DIM + g)*H_DIM + k), h1[k], s);
                h2[g] = fmaxf(s, 0.0f);
            }
            #pragma unroll
            for (int o = 0; o < O_DIM; o++) {
                float s = __ldg(fb3 + f*O_DIM + o);
                #pragma unroll
                for (int k = 0; k < H_DIM; k++)
                    s = fmaf(__ldg(fW3 + (f*O_DIM + o)*H_DIM + k), h2[k], s);
                acc[o] += s;
            }
        }
    }

    #pragma unroll
    for (int o = 0; o < O_DIM; o++) {
        acc[o] += __shfl_xor_sync(0xFFFFFFFFu, acc[o], 1);
        acc[o] += __shfl_xor_sync(0xFFFFFFFFu, acc[o], 2);
        acc[o] += __shfl_xor_sync(0xFFFFFFFFu, acc[o], 4);
        acc[o] += __shfl_xor_sync(0xFFFFFFFFu, acc[o], 8);
    }
    if ((tid & 15) == 0) {
        #pragma unroll
        for (int o = 0; o < O_DIM; o++)
            g_fsums[node * O_DIM + o] = acc[o];
    }
}

// ============================================================================
// Kernel 2: k_main — pred[i,:] = sum_j (m(d)/norm) * f_sums[j,:]
// grid=512, block=256, R=4 rows, 2 passes of 1024 j.
//   - front-batch 8 LDG.128 of d/norm per pass (MLP 16)
//   - 32KB f_sums half staged to SW128-swizzled smem, consumed via typed
//     ulonglong2 loads (compiler-visible ordering vs barriers)
//   - O-dim accumulate with fma.rn.f32x2 (4 FMA2/element)
//   - no hot-loop shuffles; tail = 2-stage smem reduction
// Slow path: honest full per-pair m-MLP.
// ============================================================================
__global__ void __launch_bounds__(256, 2)
k_main(const float* __restrict__ dmat, const float* __restrict__ nmat,
       const float* __restrict__ mW1, const float* __restrict__ mb1,
       const float* __restrict__ mW2, const float* __restrict__ mb2,
       const float* __restrict__ mW3, const float* __restrict__ mb3,
       float* __restrict__ out)
{
    __shared__ float4 s_fs[2048];        // 32KB: fs half-table, reused for tail
    __shared__ float  s_p2[8 * 32];
    __shared__ float  s_ap, s_an, s_beta;
    __shared__ int    s_fast;
    __shared__ float  sw1[H_DIM], sb1v[H_DIM], sw2[H_DIM*H_DIM], sb2v[H_DIM], sw3[H_DIM];

    const int tid = threadIdx.x;
    const int i0  = blockIdx.x * R_BLK;

    // ---- warp 0: inline m-fold + zero-bias check (full-mask butterfly) ----
    if (tid < 32) {
        const int g = tid & 15;
        float cp = 0.0f, cn = 0.0f;
        #pragma unroll
        for (int h = 0; h < H_DIM; h++) {
            const float w2 = __ldg(mW2 + g * H_DIM + h);
            const float w1 = __ldg(mW1 + h);
            cp = fmaf(w2, fmaxf(w1, 0.0f), cp);
            cn = fmaf(w2, fminf(w1, 0.0f), cn);
        }
        const float w3 = __ldg(mW3 + g);
        float ap = (tid < 16) ? w3 * fmaxf(cp, 0.0f) : 0.0f;
        float an = (tid < 16) ? w3 * fminf(cn, 0.0f) : 0.0f;
        #pragma unroll
        for (int off = 16; off > 0; off >>= 1) {
            ap += __shfl_xor_sync(0xFFFFFFFFu, ap, off);
            an += __shfl_xor_sync(0xFFFFFFFFu, an, off);
        }
        int z = (__ldg(mb1 + g) == 0.0f) & (__ldg(mb2 + g) == 0.0f);
        z = __all_sync(0xFFFFFFFFu, z);
        if (tid == 0) { s_ap = ap; s_an = an; s_beta = __ldg(mb3); s_fast = z; }
    }
    __syncthreads();

    const int   mfast = s_fast;
    const float f_ap = s_ap, f_an = s_an, f_be = s_beta;

    ull acc[R_BLK][4];
    #pragma unroll
    for (int r = 0; r < R_BLK; r++)
        #pragma unroll
        for (int p = 0; p < 4; p++) acc[r][p] = 0ull;

    if (mfast) {
        #pragma unroll
        for (int t = 0; t < 2; t++) {
            const int j0 = t * 1024 + tid * 4;

            // front-batch d/norm (8 LDG.128, streaming)
            float4 dv[R_BLK], nv[R_BLK];
            #pragma unroll
            for (int r = 0; r < R_BLK; r++) {
                dv[r] = __ldcs((const float4*)(dmat + (size_t)(i0 + r) * N_NODES + j0));
                nv[r] = __ldcs((const float4*)(nmat + (size_t)(i0 + r) * N_NODES + j0));
            }

            // stage 32KB fs half: coalesced LDG -> swizzled STS
            {
                const float4* src = (const float4*)g_fsums + t * 2048;
                #pragma unroll
                for (int q = 0; q < 8; q++) {
                    const int idx = q * 256 + tid;
                    const unsigned byte = (unsigned)idx * 16u;
                    s_fs[(byte ^ ((byte >> 3) & 0x70u)) >> 4] = __ldg(src + idx);
                }
            }
            __syncthreads();

            #pragma unroll
            for (int j = 0; j < 4; j++) {
                const unsigned byte0 = (unsigned)(tid * 4 + j) * 32u;
                const unsigned mask  = (byte0 >> 3) & 0x70u;
                const ulonglong2 pa = *(const ulonglong2*)((const char*)s_fs + (byte0 ^ mask));
                const ulonglong2 pb = *(const ulonglong2*)((const char*)s_fs + ((byte0 + 16u) ^ mask));

                #pragma unroll
                for (int r = 0; r < R_BLK; r++) {
                    const float d = (&dv[r].x)[j];
                    const float n = (&nv[r].x)[j];
                    const float m = fmaf(f_ap, fmaxf(d, 0.0f),
                                    fmaf(f_an, fminf(d, 0.0f), f_be));
                    const ull w2 = pack2(__fdividef(m, n));
                    acc[r][0] = fma2(w2, pa.x, acc[r][0]);
                    acc[r][1] = fma2(w2, pa.y, acc[r][1]);
                    acc[r][2] = fma2(w2, pb.x, acc[r][2]);
                    acc[r][3] = fma2(w2, pb.y, acc[r][3]);
                }
            }
            __syncthreads();           // before restage / tail reuse
        }
    } else {
        // ---- honest fallback: full per-pair m-MLP (never taken here) ----
        if (tid < H_DIM) {
            sw1[tid]  = mW1[tid]; sb1v[tid] = mb1[tid];
            sb2v[tid] = mb2[tid]; sw3[tid]  = mW3[tid];
        }
        sw2[tid] = mW2[tid];
        __syncthreads();
        const float b3v = mb3[0];

        for (int t = 0; t < 2; t++) {
            const int j0 = t * 1024 + tid * 4;
            float4 dv[R_BLK], nv[R_BLK];
            #pragma unroll
            for (int r = 0; r < R_BLK; r++) {
                dv[r] = __ldcs((const float4*)(dmat + (size_t)(i0 + r) * N_NODES + j0));
                nv[r] = __ldcs((const float4*)(nmat + (size_t)(i0 + r) * N_NODES + j0));
            }
            {
                const float4* src = (const float4*)g_fsums + t * 2048;
                #pragma unroll
                for (int q = 0; q < 8; q++) {
                    const int idx = q * 256 + tid;
                    const unsigned byte = (unsigned)idx * 16u;
                    s_fs[(byte ^ ((byte >> 3) & 0x70u)) >> 4] = __ldg(src + idx);
                }
            }
            __syncthreads();

            for (int j = 0; j < 4; j++) {
                const unsigned byte0 = (unsigned)(tid * 4 + j) * 32u;
                const unsigned mask  = (byte0 >> 3) & 0x70u;
                const ulonglong2 pa = *(const ulonglong2*)((const char*)s_fs + (byte0 ^ mask));
                const ulonglong2 pb = *(const ulonglong2*)((const char*)s_fs + ((byte0 + 16u) ^ mask));

                for (int r = 0; r < R_BLK; r++) {
                    const float d = (&dv[r].x)[j];
                    const float n = (&nv[r].x)[j];
                    float h1[H_DIM];
                    #pragma unroll
                    for (int k = 0; k < H_DIM; k++)
                        h1[k] = fmaxf(fmaf(d, sw1[k], sb1v[k]), 0.0f);
                    float m = b3v;
                    #pragma unroll
                    for (int g = 0; g < H_DIM; g++) {
                        float s = sb2v[g];
                        #pragma unroll
                        for (int k = 0; k < H_DIM; k++)
                            s = fmaf(sw2[g * H_DIM + k], h1[k], s);
                        m = fmaf(sw3[g], fmaxf(s, 0.0f), m);
                    }
                    const ull w2 = pack2(__fdividef(m, n));
                    acc[r][0] = fma2(w2, pa.x, acc[r][0]);
                    acc[r][1] = fma2(w2, pa.y, acc[r][1]);
                    acc[r][2] = fma2(w2, pb.x, acc[r][2]);
                    acc[r][3] = fma2(w2, pb.y, acc[r][3]);
                }
            }
            __syncthreads();
        }
    }

    // ---- tail: 2-stage smem reduction over 256 threads, reusing s_fs ----
    float* s_red = (float*)s_fs;
    {
        float a[32];
        #pragma unroll
        for (int r = 0; r < R_BLK; r++)
            #pragma unroll
            for (int p = 0; p < 4; p++)
                unpack2(acc[r][p], a[r * 8 + 2 * p], a[r * 8 + 2 * p + 1]);

        #pragma unroll
        for (int q = 0; q < 8; q++) {
            const unsigned byte = (unsigned)tid * 128u + q * 16u;
            const unsigned swz  = byte ^ (((unsigned)tid & 7u) << 4);
            *(float4*)((char*)s_red + swz) =
                make_float4(a[q*4], a[q*4+1], a[q*4+2], a[q*4+3]);
        }
    }
    __syncthreads();

    {
        const int v = tid & 31;
        const int k = tid >> 5;
        float s = 0.0f;
        #pragma unroll
        for (int m = 0; m < 32; m++) {
            const unsigned M = (unsigned)(k * 32 + m);
            const unsigned byte = M * 128u + (unsigned)v * 4u;
            const unsigned swz  = byte ^ ((M & 7u) << 4);
            s += *(const float*)((const char*)s_red + swz);
        }
        s_p2[k * 32 + v] = s;
    }
    __syncthreads();
    if (tid < 32) {
        float s = 0.0f;
        #pragma unroll
        for (int k = 0; k < 8; k++) s += s_p2[k * 32 + tid];
        out[i0 * O_DIM + tid] = s;       // tid = r*8+o
    }
}

// ============================================================================
// launch — 2 kernels
// ============================================================================
extern "C" void kernel_launch(void* const* d_in, const int* in_sizes, int n_in,
                              void* d_out, int out_size)
{
    const float* x   = (const float*)d_in[0];
    const float* dm  = (const float*)d_in[1];
    const float* nm  = (const float*)d_in[2];
    const float* fW1 = (const float*)d_in[3];
    const float* fb1 = (const float*)d_in[4];
    const float* fW2 = (const float*)d_in[5];
    const float* fb2 = (const float*)d_in[6];
    const float* fW3 = (const float*)d_in[7];
    const float* fb3 = (const float*)d_in[8];
    const float* mW1 = (const float*)d_in[9];
    const float* mb1 = (const float*)d_in[10];
    const float* mW2 = (const float*)d_in[11];
    const float* mb2 = (const float*)d_in[12];
    const float* mW3 = (const float*)d_in[13];
    const float* mb3 = (const float*)d_in[14];
    float* out = (float*)d_out;

    k_fsum<<<128, 256>>>(x, fW1, fb1, fW2, fb2, fW3, fb3);
    k_main<<<512, 256>>>(dm, nm, mW1, mb1, mW2, mb2, mW3, mb3, out);
}